// round 16
// baseline (speedup 1.0000x reference)
#include <cuda_runtime.h>
#include <cuda_fp16.h>

#define DIM 64
#define MAXN 100000
#define MAXE 1200000
#define CAP 64   // per-node bucket capacity; deg ~ Poisson(12), P(deg>=64) ~ 1e-28

// ---------------------------------------------------------------------------
// Scratch (static device globals; zero-initialized at module load).
// Invariant: g_deg == 0 at kernel_launch entry (k_agg re-zeros after use).
// g_y holds y = x @ W^T in fp16 (the linear commutes through the mean).
// g_slot[node*CAP + rank] holds the source index of that node's rank-th edge.
// Slot entries are ALWAYS valid node indices (written this launch or stale
// from a previous replay; initially 0), so speculative gathers through them
// are memory-safe; correctness comes from predicating the ACCUMULATE on deg.
// ---------------------------------------------------------------------------
__device__ int    g_deg[MAXN];
__device__ int    g_slot[(size_t)MAXN * CAP];
__device__ __half g_y[(size_t)MAXN * DIM];

// ---------------------------------------------------------------------------
// K1: fused y = x @ W^T (tensor-core HMMA, fp16 in / fp32 acc / fp16 out)
//     + direct bucket scatter (16 edges/thread for deeper atomic MLP).
// ---------------------------------------------------------------------------
__global__ __launch_bounds__(256) void k_gemm_scatter(
    const float* __restrict__ x, const float* __restrict__ W,
    const int* __restrict__ src, const int* __restrict__ dst,
    int nE, int nNodes, int gemmBlocks) {

    if (blockIdx.x < gemmBlocks) {
        __shared__ __half sA[256][72];   // x tile, fp16
        __shared__ __half sB[64][72];    // W, fp16 (row j = output col)
        int tid = threadIdx.x;
        int n0 = blockIdx.x * 256;

        for (int j = tid; j < 256 * 32; j += 256) {
            int row = j >> 5;
            int cp  = j & 31;
            int n = n0 + row;
            float2 v = (n < nNodes)
                ? *reinterpret_cast<const float2*>(x + (size_t)n * DIM + cp * 2)
                : make_float2(0.f, 0.f);
            *reinterpret_cast<__half2*>(&sA[row][cp * 2]) = __float22half2_rn(v);
        }
        for (int j = tid; j < 64 * 32; j += 256) {
            int row = j >> 5;
            int cp  = j & 31;
            float2 v = *reinterpret_cast<const float2*>(W + row * DIM + cp * 2);
            *reinterpret_cast<__half2*>(&sB[row][cp * 2]) = __float22half2_rn(v);
        }
        __syncthreads();

        int wid  = tid >> 5;
        int lane = tid & 31;
        int g  = lane >> 2;
        int qp = (lane & 3) * 2;
        int rbase = wid * 32;

        float acc[2][8][4];
        #pragma unroll
        for (int rg = 0; rg < 2; ++rg)
            #pragma unroll
            for (int nt = 0; nt < 8; ++nt)
                #pragma unroll
                for (int q = 0; q < 4; ++q)
                    acc[rg][nt][q] = 0.f;

        #pragma unroll
        for (int ks = 0; ks < 4; ++ks) {
            int kb = ks * 16 + qp;
            unsigned a[2][4];
            #pragma unroll
            for (int rg = 0; rg < 2; ++rg) {
                int r = rbase + rg * 16 + g;
                a[rg][0] = *reinterpret_cast<const unsigned*>(&sA[r][kb]);
                a[rg][1] = *reinterpret_cast<const unsigned*>(&sA[r + 8][kb]);
                a[rg][2] = *reinterpret_cast<const unsigned*>(&sA[r][kb + 8]);
                a[rg][3] = *reinterpret_cast<const unsigned*>(&sA[r + 8][kb + 8]);
            }
            #pragma unroll
            for (int nt = 0; nt < 8; ++nt) {
                int brow = nt * 8 + g;
                unsigned b0 = *reinterpret_cast<const unsigned*>(&sB[brow][kb]);
                unsigned b1 = *reinterpret_cast<const unsigned*>(&sB[brow][kb + 8]);
                #pragma unroll
                for (int rg = 0; rg < 2; ++rg) {
                    asm volatile(
                        "mma.sync.aligned.m16n8k16.row.col.f32.f16.f16.f32 "
                        "{%0,%1,%2,%3}, {%4,%5,%6,%7}, {%8,%9}, {%0,%1,%2,%3};"
                        : "+f"(acc[rg][nt][0]), "+f"(acc[rg][nt][1]),
                          "+f"(acc[rg][nt][2]), "+f"(acc[rg][nt][3])
                        : "r"(a[rg][0]), "r"(a[rg][1]),
                          "r"(a[rg][2]), "r"(a[rg][3]),
                          "r"(b0), "r"(b1));
                }
            }
        }

        #pragma unroll
        for (int rg = 0; rg < 2; ++rg) {
            int nodeA = n0 + rbase + rg * 16 + g;
            int nodeB = nodeA + 8;
            #pragma unroll
            for (int nt = 0; nt < 8; ++nt) {
                int col = nt * 8 + qp;
                if (nodeA < nNodes) {
                    __half2 hh = __float22half2_rn(
                        make_float2(acc[rg][nt][0], acc[rg][nt][1]));
                    *reinterpret_cast<unsigned*>(&g_y[(size_t)nodeA * DIM + col]) =
                        *reinterpret_cast<unsigned*>(&hh);
                }
                if (nodeB < nNodes) {
                    __half2 hh = __float22half2_rn(
                        make_float2(acc[rg][nt][2], acc[rg][nt][3]));
                    *reinterpret_cast<unsigned*>(&g_y[(size_t)nodeB * DIM + col]) =
                        *reinterpret_cast<unsigned*>(&hh);
                }
            }
        }
        return;
    }

    // ---- edge scatter section: 16 edges/thread (deep atomic MLP) ----
    int t = (blockIdx.x - gemmBlocks) * blockDim.x + threadIdx.x;
    int base = t * 16;
    if (base + 16 <= nE) {
        int d[16], s[16], r[16];
        #pragma unroll
        for (int q = 0; q < 4; ++q) {
            *reinterpret_cast<int4*>(&d[q * 4]) =
                *reinterpret_cast<const int4*>(dst + base + q * 4);
            *reinterpret_cast<int4*>(&s[q * 4]) =
                *reinterpret_cast<const int4*>(src + base + q * 4);
        }
        #pragma unroll
        for (int q = 0; q < 16; ++q)
            r[q] = atomicAdd(&g_deg[d[q]], 1);
        #pragma unroll
        for (int q = 0; q < 16; ++q)
            if (r[q] < CAP) g_slot[(size_t)d[q] * CAP + r[q]] = s[q];
    } else {
        for (int i = base; i < nE; ++i) {
            int r = atomicAdd(&g_deg[dst[i]], 1);
            if (r < CAP) g_slot[(size_t)dst[i] * CAP + r] = src[i];
        }
    }
}

// ---------------------------------------------------------------------------
// K2: terminal aggregation with SPECULATIVE first batch. 128-thread blocks
// (16 nodes each) for fine-grained scheduling — smooths the deg-variance
// wave tail (no __syncthreads, so block size is free). First 8 slot loads
// + gathers are issued before deg arrives (safe: slots always hold valid
// indices); only the accumulate is predicated. Remaining batches use
// predicated full-width loads. Re-zeros g_deg for the next launch.
// ---------------------------------------------------------------------------
__global__ __launch_bounds__(128) void k_agg(const float* __restrict__ bias,
                                             float* __restrict__ out, int n) {
    int node = (blockIdx.x * blockDim.x + threadIdx.x) >> 3;
    int l = threadIdx.x & 7;
    if (node >= n) return;

    const int* sl = g_slot + (size_t)node * CAP;
    const float4* yv = reinterpret_cast<const float4*>(g_y);  // 8 halves/elem

    // Speculative batch 1: slots + gathers issued before deg is known.
    int e[8];
    #pragma unroll
    for (int q = 0; q < 8; ++q) e[q] = __ldg(&sl[q]);

    int deg = __ldg(&g_deg[node]);      // in flight alongside the gathers

    float4 raw[8];
    #pragma unroll
    for (int q = 0; q < 8; ++q) raw[q] = yv[(size_t)e[q] * 8 + l];

    if (l == 0) g_deg[node] = 0;        // restore invariant for next launch
    int m = min(deg, CAP);

    float acc[8] = {0.f, 0.f, 0.f, 0.f, 0.f, 0.f, 0.f, 0.f};
    #pragma unroll
    for (int q = 0; q < 8; ++q) {
        if (q < m) {
            const __half2* h2 = reinterpret_cast<const __half2*>(&raw[q]);
            #pragma unroll
            for (int p = 0; p < 4; ++p) {
                float2 f = __half22float2(h2[p]);
                acc[p * 2 + 0] += f.x;
                acc[p * 2 + 1] += f.y;
            }
        }
    }

    // Remaining batches: predicated full-width (MLP stays 8, no scalar tail).
    #pragma unroll 1
    for (int i = 8; i < m; i += 8) {
        float4 rw[8];
        #pragma unroll
        for (int q = 0; q < 8; ++q) {
            int j = i + q;
            float4 r = make_float4(0.f, 0.f, 0.f, 0.f);
            if (j < m) {
                int ee = __ldg(&sl[j]);
                r = yv[(size_t)ee * 8 + l];
            }
            rw[q] = r;
        }
        #pragma unroll
        for (int q = 0; q < 8; ++q) {
            const __half2* h2 = reinterpret_cast<const __half2*>(&rw[q]);
            #pragma unroll
            for (int p = 0; p < 4; ++p) {
                float2 f = __half22float2(h2[p]);
                acc[p * 2 + 0] += f.x;
                acc[p * 2 + 1] += f.y;
            }
        }
    }

    float invd = 1.0f / fmaxf((float)deg, 1.0f);
    float4 b0 = *reinterpret_cast<const float4*>(bias + l * 8);
    float4 b1 = *reinterpret_cast<const float4*>(bias + l * 8 + 4);
    float4 o0 = make_float4(acc[0] * invd + b0.x, acc[1] * invd + b0.y,
                            acc[2] * invd + b0.z, acc[3] * invd + b0.w);
    float4 o1 = make_float4(acc[4] * invd + b1.x, acc[5] * invd + b1.y,
                            acc[6] * invd + b1.z, acc[7] * invd + b1.w);
    float4* po = reinterpret_cast<float4*>(out + (size_t)node * DIM + l * 8);
    po[0] = o0;
    po[1] = o1;
}

// ---------------------------------------------------------------------------
// Launch. Inputs: x [N*64 f32], src [E i32], dst [E i32], W [64*64 f32],
// b [64 f32]. Output: [N*64 f32]. TWO kernels total.
// ---------------------------------------------------------------------------
extern "C" void kernel_launch(void* const* d_in, const int* in_sizes, int n_in,
                              void* d_out, int out_size) {
    const float* x   = (const float*)d_in[0];
    const int*   src = (const int*)d_in[1];
    const int*   dst = (const int*)d_in[2];
    const float* W   = (const float*)d_in[3];
    const float* b   = (const float*)d_in[4];
    float* out = (float*)d_out;

    int nNodes = in_sizes[0] / DIM;
    int nEdges = in_sizes[1];

    int gemmBlocks = (nNodes + 255) / 256;
    int edgeBlocks = ((nEdges + 15) / 16 + 255) / 256;

    k_gemm_scatter<<<gemmBlocks + edgeBlocks, 256>>>(x, W, src, dst,
                                                     nEdges, nNodes, gemmBlocks);
    k_agg<<<(nNodes * 8 + 127) / 128, 128>>>(b, out, nNodes);
}

// round 17
// speedup vs baseline: 1.0686x; 1.0686x over previous
#include <cuda_runtime.h>
#include <cuda_fp16.h>

#define DIM 64
#define MAXN 100000
#define MAXE 1200000
#define CAP 64   // per-node bucket capacity; deg ~ Poisson(12), P(deg>=64) ~ 1e-28

// ---------------------------------------------------------------------------
// Scratch (static device globals; zero-initialized at module load).
// Invariant: g_deg == 0 at kernel_launch entry (k_agg re-zeros after use).
// g_y holds y = x @ W^T in fp16 (the linear commutes through the mean).
// g_slot[node*CAP + rank] holds the source index of that node's rank-th edge.
// Slot entries are ALWAYS valid node indices (written this launch or stale
// from a previous replay; initially 0), so speculative gathers through them
// are memory-safe; correctness comes from predicating the ACCUMULATE on deg.
// ---------------------------------------------------------------------------
__device__ int    g_deg[MAXN];
__device__ int    g_slot[(size_t)MAXN * CAP];
__device__ __half g_y[(size_t)MAXN * DIM];

// ---------------------------------------------------------------------------
// K1: fused edge scatter + y = x @ W^T (tensor-core HMMA).
// Blocks [0, edgeBlocks): scatter, 8 edges/thread — FIRST in the grid so the
//   latency-bound atomic stream starts immediately and overlaps the gemm.
// Blocks [edgeBlocks, ...): 256-node x 64-col GEMM tiles -> g_y (fp16).
// ---------------------------------------------------------------------------
__global__ __launch_bounds__(256) void k_scatter_gemm(
    const float* __restrict__ x, const float* __restrict__ W,
    const int* __restrict__ src, const int* __restrict__ dst,
    int nE, int nNodes, int edgeBlocks) {

    if (blockIdx.x < edgeBlocks) {
        // ---- edge scatter section: 8 edges/thread ----
        int t = blockIdx.x * blockDim.x + threadIdx.x;
        int i8 = t * 8;
        if (i8 + 8 <= nE) {
            int4 d0 = *reinterpret_cast<const int4*>(dst + i8);
            int4 d1 = *reinterpret_cast<const int4*>(dst + i8 + 4);
            int4 s0 = *reinterpret_cast<const int4*>(src + i8);
            int4 s1 = *reinterpret_cast<const int4*>(src + i8 + 4);
            int r0 = atomicAdd(&g_deg[d0.x], 1);
            int r1 = atomicAdd(&g_deg[d0.y], 1);
            int r2 = atomicAdd(&g_deg[d0.z], 1);
            int r3 = atomicAdd(&g_deg[d0.w], 1);
            int r4 = atomicAdd(&g_deg[d1.x], 1);
            int r5 = atomicAdd(&g_deg[d1.y], 1);
            int r6 = atomicAdd(&g_deg[d1.z], 1);
            int r7 = atomicAdd(&g_deg[d1.w], 1);
            if (r0 < CAP) g_slot[(size_t)d0.x * CAP + r0] = s0.x;
            if (r1 < CAP) g_slot[(size_t)d0.y * CAP + r1] = s0.y;
            if (r2 < CAP) g_slot[(size_t)d0.z * CAP + r2] = s0.z;
            if (r3 < CAP) g_slot[(size_t)d0.w * CAP + r3] = s0.w;
            if (r4 < CAP) g_slot[(size_t)d1.x * CAP + r4] = s1.x;
            if (r5 < CAP) g_slot[(size_t)d1.y * CAP + r5] = s1.y;
            if (r6 < CAP) g_slot[(size_t)d1.z * CAP + r6] = s1.z;
            if (r7 < CAP) g_slot[(size_t)d1.w * CAP + r7] = s1.w;
        } else {
            for (int i = i8; i < nE; ++i) {
                int r = atomicAdd(&g_deg[dst[i]], 1);
                if (r < CAP) g_slot[(size_t)dst[i] * CAP + r] = src[i];
            }
        }
        return;
    }

    // ---- GEMM section ----
    __shared__ __half sA[256][72];   // x tile, fp16
    __shared__ __half sB[64][72];    // W, fp16 (row j = output col)
    int tid = threadIdx.x;
    int n0 = (blockIdx.x - edgeBlocks) * 256;

    for (int j = tid; j < 256 * 32; j += 256) {
        int row = j >> 5;
        int cp  = j & 31;
        int n = n0 + row;
        float2 v = (n < nNodes)
            ? *reinterpret_cast<const float2*>(x + (size_t)n * DIM + cp * 2)
            : make_float2(0.f, 0.f);
        *reinterpret_cast<__half2*>(&sA[row][cp * 2]) = __float22half2_rn(v);
    }
    for (int j = tid; j < 64 * 32; j += 256) {
        int row = j >> 5;
        int cp  = j & 31;
        float2 v = *reinterpret_cast<const float2*>(W + row * DIM + cp * 2);
        *reinterpret_cast<__half2*>(&sB[row][cp * 2]) = __float22half2_rn(v);
    }
    __syncthreads();

    int wid  = tid >> 5;
    int lane = tid & 31;
    int g  = lane >> 2;
    int qp = (lane & 3) * 2;
    int rbase = wid * 32;

    float acc[2][8][4];
    #pragma unroll
    for (int rg = 0; rg < 2; ++rg)
        #pragma unroll
        for (int nt = 0; nt < 8; ++nt)
            #pragma unroll
            for (int q = 0; q < 4; ++q)
                acc[rg][nt][q] = 0.f;

    #pragma unroll
    for (int ks = 0; ks < 4; ++ks) {
        int kb = ks * 16 + qp;
        unsigned a[2][4];
        #pragma unroll
        for (int rg = 0; rg < 2; ++rg) {
            int r = rbase + rg * 16 + g;
            a[rg][0] = *reinterpret_cast<const unsigned*>(&sA[r][kb]);
            a[rg][1] = *reinterpret_cast<const unsigned*>(&sA[r + 8][kb]);
            a[rg][2] = *reinterpret_cast<const unsigned*>(&sA[r][kb + 8]);
            a[rg][3] = *reinterpret_cast<const unsigned*>(&sA[r + 8][kb + 8]);
        }
        #pragma unroll
        for (int nt = 0; nt < 8; ++nt) {
            int brow = nt * 8 + g;
            unsigned b0 = *reinterpret_cast<const unsigned*>(&sB[brow][kb]);
            unsigned b1 = *reinterpret_cast<const unsigned*>(&sB[brow][kb + 8]);
            #pragma unroll
            for (int rg = 0; rg < 2; ++rg) {
                asm volatile(
                    "mma.sync.aligned.m16n8k16.row.col.f32.f16.f16.f32 "
                    "{%0,%1,%2,%3}, {%4,%5,%6,%7}, {%8,%9}, {%0,%1,%2,%3};"
                    : "+f"(acc[rg][nt][0]), "+f"(acc[rg][nt][1]),
                      "+f"(acc[rg][nt][2]), "+f"(acc[rg][nt][3])
                    : "r"(a[rg][0]), "r"(a[rg][1]),
                      "r"(a[rg][2]), "r"(a[rg][3]),
                      "r"(b0), "r"(b1));
            }
        }
    }

    #pragma unroll
    for (int rg = 0; rg < 2; ++rg) {
        int nodeA = n0 + rbase + rg * 16 + g;
        int nodeB = nodeA + 8;
        #pragma unroll
        for (int nt = 0; nt < 8; ++nt) {
            int col = nt * 8 + qp;
            if (nodeA < nNodes) {
                __half2 hh = __float22half2_rn(
                    make_float2(acc[rg][nt][0], acc[rg][nt][1]));
                *reinterpret_cast<unsigned*>(&g_y[(size_t)nodeA * DIM + col]) =
                    *reinterpret_cast<unsigned*>(&hh);
            }
            if (nodeB < nNodes) {
                __half2 hh = __float22half2_rn(
                    make_float2(acc[rg][nt][2], acc[rg][nt][3]));
                *reinterpret_cast<unsigned*>(&g_y[(size_t)nodeB * DIM + col]) =
                    *reinterpret_cast<unsigned*>(&hh);
            }
        }
    }
}

// ---------------------------------------------------------------------------
// K2: terminal aggregation with SPECULATIVE first batch + packed f32x2
// accumulation (add.rn.f32x2 — Blackwell packed fp32 add; exact fp32, 25%
// fewer issue slots on the convert/accumulate stream where this kernel is
// issue-bound). 128-thread blocks. Re-zeros g_deg for the next launch.
// ---------------------------------------------------------------------------
__device__ __forceinline__ void acc_f32x2(unsigned long long& a, float lo, float hi) {
    unsigned long long v;
    asm("mov.b64 %0, {%1, %2};" : "=l"(v) : "f"(lo), "f"(hi));
    asm("add.rn.f32x2 %0, %0, %1;" : "+l"(a) : "l"(v));
}

__global__ __launch_bounds__(128) void k_agg(const float* __restrict__ bias,
                                             float* __restrict__ out, int n) {
    int node = (blockIdx.x * blockDim.x + threadIdx.x) >> 3;
    int l = threadIdx.x & 7;
    if (node >= n) return;

    const int* sl = g_slot + (size_t)node * CAP;
    const float4* yv = reinterpret_cast<const float4*>(g_y);  // 8 halves/elem

    // Speculative batch 1: slots + gathers issued before deg is known.
    int e[8];
    #pragma unroll
    for (int q = 0; q < 8; ++q) e[q] = __ldg(&sl[q]);

    int deg = __ldg(&g_deg[node]);      // in flight alongside the gathers

    float4 raw[8];
    #pragma unroll
    for (int q = 0; q < 8; ++q) raw[q] = yv[(size_t)e[q] * 8 + l];

    if (l == 0) g_deg[node] = 0;        // restore invariant for next launch
    int m = min(deg, CAP);

    unsigned long long acc2[4];         // 4 packed f32x2 accumulators
    #pragma unroll
    for (int p = 0; p < 4; ++p)
        asm("mov.b64 %0, {%1, %1};" : "=l"(acc2[p]) : "f"(0.0f));

    #pragma unroll
    for (int q = 0; q < 8; ++q) {
        if (q < m) {
            const __half2* h2 = reinterpret_cast<const __half2*>(&raw[q]);
            #pragma unroll
            for (int p = 0; p < 4; ++p) {
                float2 f = __half22float2(h2[p]);
                acc_f32x2(acc2[p], f.x, f.y);
            }
        }
    }

    // Remaining batches: predicated full-width (MLP stays 8, no scalar tail).
    #pragma unroll 1
    for (int i = 8; i < m; i += 8) {
        float4 rw[8];
        #pragma unroll
        for (int q = 0; q < 8; ++q) {
            int j = i + q;
            float4 r = make_float4(0.f, 0.f, 0.f, 0.f);
            if (j < m) {
                int ee = __ldg(&sl[j]);
                r = yv[(size_t)ee * 8 + l];
            }
            rw[q] = r;
        }
        #pragma unroll
        for (int q = 0; q < 8; ++q) {
            const __half2* h2 = reinterpret_cast<const __half2*>(&rw[q]);
            #pragma unroll
            for (int p = 0; p < 4; ++p) {
                float2 f = __half22float2(h2[p]);
                acc_f32x2(acc2[p], f.x, f.y);
            }
        }
    }

    float acc[8];
    #pragma unroll
    for (int p = 0; p < 4; ++p)
        asm("mov.b64 {%0, %1}, %2;" : "=f"(acc[p * 2]), "=f"(acc[p * 2 + 1])
            : "l"(acc2[p]));

    float invd = 1.0f / fmaxf((float)deg, 1.0f);
    float4 b0 = *reinterpret_cast<const float4*>(bias + l * 8);
    float4 b1 = *reinterpret_cast<const float4*>(bias + l * 8 + 4);
    float4 o0 = make_float4(acc[0] * invd + b0.x, acc[1] * invd + b0.y,
                            acc[2] * invd + b0.z, acc[3] * invd + b0.w);
    float4 o1 = make_float4(acc[4] * invd + b1.x, acc[5] * invd + b1.y,
                            acc[6] * invd + b1.z, acc[7] * invd + b1.w);
    float4* po = reinterpret_cast<float4*>(out + (size_t)node * DIM + l * 8);
    po[0] = o0;
    po[1] = o1;
}

// ---------------------------------------------------------------------------
// Launch. Inputs: x [N*64 f32], src [E i32], dst [E i32], W [64*64 f32],
// b [64 f32]. Output: [N*64 f32]. TWO kernels total.
// ---------------------------------------------------------------------------
extern "C" void kernel_launch(void* const* d_in, const int* in_sizes, int n_in,
                              void* d_out, int out_size) {
    const float* x   = (const float*)d_in[0];
    const int*   src = (const int*)d_in[1];
    const int*   dst = (const int*)d_in[2];
    const float* W   = (const float*)d_in[3];
    const float* b   = (const float*)d_in[4];
    float* out = (float*)d_out;

    int nNodes = in_sizes[0] / DIM;
    int nEdges = in_sizes[1];

    int gemmBlocks = (nNodes + 255) / 256;
    int edgeBlocks = ((nEdges + 7) / 8 + 255) / 256;

    k_scatter_gemm<<<edgeBlocks + gemmBlocks, 256>>>(x, W, src, dst,
                                                     nEdges, nNodes, edgeBlocks);
    k_agg<<<(nNodes * 8 + 127) / 128, 128>>>(b, out, nNodes);
}